// round 5
// baseline (speedup 1.0000x reference)
#include <cuda_runtime.h>
#include <cuda_fp16.h>

#define NN 100000
#define NE 1600000
#define NG 256
#define HID 64

// ---- static scratch (no allocations allowed) ----
__device__ __align__(16) __half g_xwh[NN * HID];   // fp16 transformed features
__device__ __align__(128) float g_agg[NN * HID];   // single ping buffer (fp32)
__device__ float g_deg[NN];        // deg, then overwritten with dinv = rsqrt(deg)
__device__ int   g_hist[NN];       // in-degree histogram
__device__ int   g_row[NN + 1];    // CSR row offsets (by dst)
__device__ int   g_cursor[NN];     // counting-sort cursors
__device__ int   g_bsum[128];      // scan block sums
__device__ __align__(8) int2 g_edge[NE];  // CSR record: (src, norm-as-bits)
__device__ float g_sums[NG];
__device__ float g_cnt[NG];

// -------------------- init --------------------
__global__ void k_init(int n) {
    int i = blockIdx.x * blockDim.x + threadIdx.x;
    if (i < n) { g_deg[i] = 1.0f; g_hist[i] = 0; }
    if (i < NG) { g_sums[i] = 0.f; g_cnt[i] = 0.f; }
}

// -------------------- degree + histogram (one pass over edges) --------------------
__global__ void k_deg_hist(const int* __restrict__ dst, const float* __restrict__ w, int E) {
    int e = blockIdx.x * blockDim.x + threadIdx.x;
    if (e < E) {
        int d = dst[e];
        atomicAdd(&g_deg[d], w[e]);
        atomicAdd(&g_hist[d], 1);
    }
}

// -------------------- 2-level exclusive scan of g_hist -> g_row --------------------
__global__ __launch_bounds__(1024) void k_scanA(int n) {
    __shared__ int ws[32];
    int t = threadIdx.x;
    int i = blockIdx.x * 1024 + t;
    int v = (i < n) ? g_hist[i] : 0;
    const unsigned full = 0xffffffffu;
    int lane = t & 31, warp = t >> 5;
    int x = v;
    #pragma unroll
    for (int off = 1; off < 32; off <<= 1) {
        int y = __shfl_up_sync(full, x, off);
        if (lane >= off) x += y;
    }
    if (lane == 31) ws[warp] = x;
    __syncthreads();
    if (warp == 0) {
        int y = ws[lane];
        #pragma unroll
        for (int off = 1; off < 32; off <<= 1) {
            int z = __shfl_up_sync(full, y, off);
            if (lane >= off) y += z;
        }
        ws[lane] = y;
    }
    __syncthreads();
    int blockpref = (warp > 0) ? ws[warp - 1] : 0;
    int incl = x + blockpref;
    if (i < n) g_row[i] = incl - v;
    if (t == 1023) g_bsum[blockIdx.x] = incl;
}

__global__ void k_scanB(int nb) {
    if (threadIdx.x == 0) {
        int acc = 0;
        for (int b = 0; b < nb; b++) { int v = g_bsum[b]; g_bsum[b] = acc; acc += v; }
    }
}

// also finalizes dinv = rsqrt(deg) here (merged k_dinv)
__global__ __launch_bounds__(1024) void k_scanC(int n, int E) {
    int i = blockIdx.x * 1024 + threadIdx.x;
    if (i < n) {
        int r = g_row[i] + g_bsum[blockIdx.x];
        g_row[i] = r;
        g_cursor[i] = r;
        g_deg[i] = rsqrtf(g_deg[i]);
    }
    if (i == 0) g_row[n] = E;
}

// -------------------- counting-sort fill: packed (src, norm) by dst --------------------
__global__ void k_fill(const int* __restrict__ src, const int* __restrict__ dst,
                       const float* __restrict__ w, int E) {
    int e = blockIdx.x * blockDim.x + threadIdx.x;
    if (e < E) {
        int s = src[e], d = dst[e];
        float nv = g_deg[s] * w[e] * g_deg[d];   // g_deg holds dinv
        int pos = atomicAdd(&g_cursor[d], 1);
        int2 rec; rec.x = s; rec.y = __float_as_int(nv);
        g_edge[pos] = rec;
    }
}

// -------------------- GEMM: xwh = half( act(X) @ W ) --------------------
__global__ __launch_bounds__(256) void k_gemm(
    const float* __restrict__ Xext, const float* __restrict__ W,
    int use_ext, int relu_in, int n)
{
    __shared__ float Ws[64 * 64];
    __shared__ float Xs[64 * 65];

    const float* X = use_ext ? Xext : g_agg;

    int tid = threadIdx.x;
    int row0 = blockIdx.x * 64;

    const float4* W4 = (const float4*)W;
    float4* Ws4 = (float4*)Ws;
    #pragma unroll
    for (int i = 0; i < 4; i++) Ws4[tid + 256 * i] = W4[tid + 256 * i];

    const float4* X4 = (const float4*)(X + (size_t)row0 * 64);
    #pragma unroll
    for (int i = 0; i < 4; i++) {
        int idx = tid + 256 * i;
        int r = idx >> 4, c4 = idx & 15;
        if (row0 + r < n) {
            float4 v = X4[idx];
            if (relu_in) {
                v.x = fmaxf(v.x, 0.f); v.y = fmaxf(v.y, 0.f);
                v.z = fmaxf(v.z, 0.f); v.w = fmaxf(v.w, 0.f);
            }
            float* p = &Xs[r * 65 + c4 * 4];
            p[0] = v.x; p[1] = v.y; p[2] = v.z; p[3] = v.w;
        }
    }
    __syncthreads();

    int r = tid >> 2;
    int cs = (tid & 3) * 16;
    int row = row0 + r;
    if (row >= n) return;

    float acc[16];
    #pragma unroll
    for (int c = 0; c < 16; c++) acc[c] = 0.f;

    #pragma unroll
    for (int k = 0; k < 64; k++) {
        float xv = Xs[r * 65 + k];
        const float4* wr = (const float4*)&Ws[k * 64 + cs];
        #pragma unroll
        for (int c4 = 0; c4 < 4; c4++) {
            float4 wv = wr[c4];
            acc[c4 * 4 + 0] += xv * wv.x;
            acc[c4 * 4 + 1] += xv * wv.y;
            acc[c4 * 4 + 2] += xv * wv.z;
            acc[c4 * 4 + 3] += xv * wv.w;
        }
    }

    __half2 hh[8];
    #pragma unroll
    for (int i = 0; i < 8; i++)
        hh[i] = __floats2half2_rn(acc[2 * i], acc[2 * i + 1]);
    uint4* dstp = (uint4*)(g_xwh + (size_t)row * 64 + cs);
    dstp[0] = ((uint4*)hh)[0];
    dstp[1] = ((uint4*)hh)[1];
}

// ---- shared gather core: 8 threads/node, each accumulates 8 features in fp32 ----
__device__ __forceinline__ void gather_core(int node, int j, const float* __restrict__ bias,
                                            float* a /*[8]*/)
{
    int start = __ldg(g_row + node);
    int end   = __ldg(g_row + node + 1);
    float dv = __ldg(g_deg + node);
    float inv = dv * dv;

    const uint4* xw = (const uint4*)g_xwh;   // 16B = 8 halfs per slot, 8 slots/row

    // bias + self-loop
    {
        uint4 v = __ldg(&xw[(size_t)node * 8 + j]);
        const __half2* h = (const __half2*)&v;
        const float4* b4 = (const float4*)(bias + j * 8);
        float4 b0 = __ldg(b4), b1 = __ldg(b4 + 1);
        float2 f0 = __half22float2(h[0]), f1 = __half22float2(h[1]);
        float2 f2 = __half22float2(h[2]), f3 = __half22float2(h[3]);
        a[0] = f0.x * inv + b0.x; a[1] = f0.y * inv + b0.y;
        a[2] = f1.x * inv + b0.z; a[3] = f1.y * inv + b0.w;
        a[4] = f2.x * inv + b1.x; a[5] = f2.y * inv + b1.y;
        a[6] = f3.x * inv + b1.z; a[7] = f3.y * inv + b1.w;
    }

    int e = start;
    for (; e + 3 < end; e += 4) {
        int2 p0 = __ldg(g_edge + e);
        int2 p1 = __ldg(g_edge + e + 1);
        int2 p2 = __ldg(g_edge + e + 2);
        int2 p3 = __ldg(g_edge + e + 3);
        uint4 v0 = __ldg(&xw[(size_t)p0.x * 8 + j]);
        uint4 v1 = __ldg(&xw[(size_t)p1.x * 8 + j]);
        uint4 v2 = __ldg(&xw[(size_t)p2.x * 8 + j]);
        uint4 v3 = __ldg(&xw[(size_t)p3.x * 8 + j]);
        #pragma unroll
        for (int q = 0; q < 4; q++) {
            uint4 v = (q == 0) ? v0 : (q == 1) ? v1 : (q == 2) ? v2 : v3;
            float nv = __int_as_float((q == 0) ? p0.y : (q == 1) ? p1.y : (q == 2) ? p2.y : p3.y);
            const __half2* h = (const __half2*)&v;
            float2 f0 = __half22float2(h[0]), f1 = __half22float2(h[1]);
            float2 f2 = __half22float2(h[2]), f3 = __half22float2(h[3]);
            a[0] += f0.x * nv; a[1] += f0.y * nv;
            a[2] += f1.x * nv; a[3] += f1.y * nv;
            a[4] += f2.x * nv; a[5] += f2.y * nv;
            a[6] += f3.x * nv; a[7] += f3.y * nv;
        }
    }
    for (; e < end; e++) {
        int2 p = __ldg(g_edge + e);
        float nv = __int_as_float(p.y);
        uint4 v = __ldg(&xw[(size_t)p.x * 8 + j]);
        const __half2* h = (const __half2*)&v;
        float2 f0 = __half22float2(h[0]), f1 = __half22float2(h[1]);
        float2 f2 = __half22float2(h[2]), f3 = __half22float2(h[3]);
        a[0] += f0.x * nv; a[1] += f0.y * nv;
        a[2] += f1.x * nv; a[3] += f1.y * nv;
        a[4] += f2.x * nv; a[5] += f2.y * nv;
        a[6] += f3.x * nv; a[7] += f3.y * nv;
    }
}

// -------------------- gather -> g_agg (layers 0,1) --------------------
__global__ __launch_bounds__(256) void k_gather(const float* __restrict__ bias, int n)
{
    int t = blockIdx.x * blockDim.x + threadIdx.x;
    int node = t >> 3;
    if (node >= n) return;
    int j = t & 7;

    float a[8];
    gather_core(node, j, bias, a);

    float4* out = (float4*)(g_agg + (size_t)node * 64 + j * 8);
    float4 o0; o0.x = a[0]; o0.y = a[1]; o0.z = a[2]; o0.w = a[3];
    float4 o1; o1.x = a[4]; o1.y = a[5]; o1.z = a[6]; o1.w = a[7];
    out[0] = o0; out[1] = o1;
}

// -------------------- fused final gather + MLP readout + pooling --------------------
// 256 threads = 32 nodes x 8 threads
__global__ __launch_bounds__(256) void k_gather_readout(
    const float* __restrict__ bias,
    const float* __restrict__ Wr0, const float* __restrict__ br0,
    const float* __restrict__ Wr1, const float* __restrict__ br1,
    const int* __restrict__ batch, int n)
{
    __shared__ float aggS[32][72];     // pitch 72: 16B-aligned rows, conflict-safe
    __shared__ float W0s[64 * 32];
    __shared__ float W1s[32];
    __shared__ float b0s[32];

    int tid = threadIdx.x;
    for (int i = tid; i < 2048; i += 256) W0s[i] = Wr0[i];
    if (tid < 32) { W1s[tid] = Wr1[tid]; b0s[tid] = br0[tid]; }

    int node_l = tid >> 3;
    int j = tid & 7;
    int node = blockIdx.x * 32 + node_l;
    bool valid = (node < n);

    if (valid) {
        float a[8];
        gather_core(node, j, bias, a);
        float* row = &aggS[node_l][j * 8];
        #pragma unroll
        for (int q = 0; q < 8; q++) row[q] = a[q];
    }
    __syncthreads();

    // readout: thread computes 4 hidden cols of its node
    float s = 0.f, cv = 0.f;
    int g = -1;
    if (valid) {
        int c0 = j * 4;
        float acc0 = b0s[c0], acc1 = b0s[c0 + 1], acc2 = b0s[c0 + 2], acc3 = b0s[c0 + 3];
        const float* row = aggS[node_l];
        #pragma unroll
        for (int k = 0; k < 64; k++) {
            float v = row[k];
            const float4 wv = *(const float4*)&W0s[k * 32 + c0];
            acc0 += v * wv.x; acc1 += v * wv.y; acc2 += v * wv.z; acc3 += v * wv.w;
        }
        const float4 w1 = *(const float4*)&W1s[c0];
        s = fmaxf(acc0, 0.f) * w1.x + fmaxf(acc1, 0.f) * w1.y
          + fmaxf(acc2, 0.f) * w1.z + fmaxf(acc3, 0.f) * w1.w;
        g = __ldg(batch + node);
    }

    // reduce the 8 partial sums of each node (xor within aligned 8-lane group)
    const unsigned full = 0xffffffffu;
    s += __shfl_xor_sync(full, s, 4);
    s += __shfl_xor_sync(full, s, 2);
    s += __shfl_xor_sync(full, s, 1);

    // keep contribution only on lane j==0 of each node; add final bias there
    if (valid && j == 0) { s += __ldg(br1); cv = 1.f; }
    else { s = 0.f; }

    // warp segmented scan over sorted graph ids (4 nodes per warp)
    int lane = tid & 31;
    #pragma unroll
    for (int off = 1; off < 32; off <<= 1) {
        float so = __shfl_up_sync(full, s, off);
        float co = __shfl_up_sync(full, cv, off);
        int go = __shfl_up_sync(full, g, off);
        if (lane >= off && go == g) { s += so; cv += co; }
    }
    int gn = __shfl_down_sync(full, g, 1);
    if ((lane == 31 || gn != g) && g >= 0) {
        atomicAdd(&g_sums[g], s);
        atomicAdd(&g_cnt[g], cv);
    }
}

__global__ void k_finalize(float* __restrict__ out) {
    int g = threadIdx.x;
    out[g] = g_sums[g] / fmaxf(g_cnt[g], 1.0f);
}

// -------------------- launch --------------------
extern "C" void kernel_launch(void* const* d_in, const int* in_sizes, int n_in,
                              void* d_out, int out_size)
{
    const float* x   = (const float*)d_in[0];
    const int*   ei  = (const int*)d_in[1];
    const float* ew  = (const float*)d_in[2];
    const int* batch = (const int*)d_in[3];
    const float* W0  = (const float*)d_in[4];
    const float* b0  = (const float*)d_in[5];
    const float* W1  = (const float*)d_in[6];
    const float* b1  = (const float*)d_in[7];
    const float* W2  = (const float*)d_in[8];
    const float* b2  = (const float*)d_in[9];
    const float* Wr0 = (const float*)d_in[10];
    const float* br0 = (const float*)d_in[11];
    const float* Wr1 = (const float*)d_in[12];
    const float* br1 = (const float*)d_in[13];
    float* out = (float*)d_out;

    int n = in_sizes[0] / HID;       // 100000
    int E = in_sizes[2];             // 1600000
    const int* src = ei;
    const int* dst = ei + E;

    int nb = (n + 1023) / 1024;

    // ---- CSR build ----
    k_init<<<(n + 255) / 256, 256>>>(n);
    k_deg_hist<<<(E + 255) / 256, 256>>>(dst, ew, E);
    k_scanA<<<nb, 1024>>>(n);
    k_scanB<<<1, 32>>>(nb);
    k_scanC<<<nb, 1024>>>(n, E);
    k_fill<<<(E + 255) / 256, 256>>>(src, dst, ew, E);

    int gb = (n + 63) / 64;
    int ga = (n * 8 + 255) / 256;
    int gf = (n + 31) / 32;

    // layer 0: x -> agg
    k_gemm<<<gb, 256>>>(x, W0, 1, 0, n);
    k_gather<<<ga, 256>>>(b0, n);
    // layer 1: relu(agg) -> agg
    k_gemm<<<gb, 256>>>(nullptr, W1, 0, 1, n);
    k_gather<<<ga, 256>>>(b1, n);
    // layer 2: relu(agg) -> fused gather + readout + pooling
    k_gemm<<<gb, 256>>>(nullptr, W2, 0, 1, n);
    k_gather_readout<<<gf, 256>>>(b2, Wr0, br0, Wr1, br1, batch, n);

    k_finalize<<<1, 256>>>(out);
}

// round 6
// speedup vs baseline: 1.0221x; 1.0221x over previous
#include <cuda_runtime.h>
#include <cuda_fp16.h>

#define NN 100000
#define NE 1600000
#define NG 256
#define HID 64

// ---- static scratch (no allocations allowed) ----
__device__ __align__(16) __half g_xwA[NN * HID];   // fp16 transformed features (ping)
__device__ __align__(16) __half g_xwB[NN * HID];   // fp16 transformed features (pong)
__device__ unsigned long long g_packed[NN];        // [40:64)=in-degree count, [0:40)=sum(w) Q24
__device__ float g_deg[NN];                        // dinv = rsqrt(deg)
__device__ int   g_row[NN + 1];                    // CSR row offsets (by dst)
__device__ int   g_rank[NE];                       // per-edge rank within its dst bucket
__device__ int   g_bsum[128];                      // scan block sums
__device__ __align__(8) int2 g_edge[NE];           // CSR record: (src, norm-as-bits)
__device__ float g_sums[NG];
__device__ float g_cnt[NG];

#define Q24 16777216.0f

// -------------------- init --------------------
__global__ void k_init(int n) {
    int i = blockIdx.x * blockDim.x + threadIdx.x;
    if (i < n) g_packed[i] = 0ull;
    if (i < NG) { g_sums[i] = 0.f; g_cnt[i] = 0.f; }
}

// -------------------- single packed atomic: deg + hist + rank --------------------
__global__ void k_deg_hist(const int* __restrict__ dst, const float* __restrict__ w, int E) {
    int e = blockIdx.x * blockDim.x + threadIdx.x;
    if (e < E) {
        int d = dst[e];
        unsigned long long add =
            (1ull << 40) | (unsigned long long)__float2uint_rn(w[e] * Q24);
        unsigned long long old = atomicAdd(&g_packed[d], add);
        g_rank[e] = (int)(old >> 40);
    }
}

// -------------------- 2-level exclusive scan of counts -> g_row --------------------
__global__ __launch_bounds__(1024) void k_scanA(int n) {
    __shared__ int ws[32];
    int t = threadIdx.x;
    int i = blockIdx.x * 1024 + t;
    int v = (i < n) ? (int)(g_packed[i] >> 40) : 0;
    const unsigned full = 0xffffffffu;
    int lane = t & 31, warp = t >> 5;
    int x = v;
    #pragma unroll
    for (int off = 1; off < 32; off <<= 1) {
        int y = __shfl_up_sync(full, x, off);
        if (lane >= off) x += y;
    }
    if (lane == 31) ws[warp] = x;
    __syncthreads();
    if (warp == 0) {
        int y = ws[lane];
        #pragma unroll
        for (int off = 1; off < 32; off <<= 1) {
            int z = __shfl_up_sync(full, y, off);
            if (lane >= off) y += z;
        }
        ws[lane] = y;
    }
    __syncthreads();
    int blockpref = (warp > 0) ? ws[warp - 1] : 0;
    int incl = x + blockpref;
    if (i < n) g_row[i] = incl - v;
    if (t == 1023) g_bsum[blockIdx.x] = incl;
}

__global__ __launch_bounds__(128) void k_scanB(int nb) {
    __shared__ int ws[4];
    int t = threadIdx.x;
    int v = (t < nb) ? g_bsum[t] : 0;
    const unsigned full = 0xffffffffu;
    int lane = t & 31, warp = t >> 5;
    int x = v;
    #pragma unroll
    for (int off = 1; off < 32; off <<= 1) {
        int y = __shfl_up_sync(full, x, off);
        if (lane >= off) x += y;
    }
    if (lane == 31) ws[warp] = x;
    __syncthreads();
    if (t == 0) { int a = 0; for (int i = 0; i < 4; i++) { int u = ws[i]; ws[i] = a; a += u; } }
    __syncthreads();
    if (t < nb) g_bsum[t] = x - v + ws[warp];
}

// finalize row offsets + dinv
__global__ __launch_bounds__(1024) void k_scanC(int n, int E) {
    int i = blockIdx.x * 1024 + threadIdx.x;
    if (i < n) {
        g_row[i] += g_bsum[blockIdx.x];
        float deg = 1.0f + (float)(g_packed[i] & 0xFFFFFFFFFFull) * (1.0f / Q24);
        g_deg[i] = rsqrtf(deg);
    }
    if (i == 0) g_row[n] = E;
}

// -------------------- atomic-free counting-sort fill --------------------
__global__ void k_fill(const int* __restrict__ src, const int* __restrict__ dst,
                       const float* __restrict__ w, int E) {
    int e = blockIdx.x * blockDim.x + threadIdx.x;
    if (e < E) {
        int s = src[e], d = dst[e];
        float nv = g_deg[s] * w[e] * g_deg[d];
        int pos = __ldg(g_row + d) + g_rank[e];
        int2 rec; rec.x = s; rec.y = __float_as_int(nv);
        g_edge[pos] = rec;
    }
}

// -------------------- layer-0 GEMM: xwA = x @ W0 (fp16 out) --------------------
__global__ __launch_bounds__(256) void k_gemm0(
    const float* __restrict__ X, const float* __restrict__ W, int n)
{
    __shared__ float Ws[64 * 64];
    __shared__ float Xs[64 * 65];

    int tid = threadIdx.x;
    int row0 = blockIdx.x * 64;

    const float4* W4 = (const float4*)W;
    float4* Ws4 = (float4*)Ws;
    #pragma unroll
    for (int i = 0; i < 4; i++) Ws4[tid + 256 * i] = W4[tid + 256 * i];

    const float4* X4 = (const float4*)(X + (size_t)row0 * 64);
    #pragma unroll
    for (int i = 0; i < 4; i++) {
        int idx = tid + 256 * i;
        int r = idx >> 4, c4 = idx & 15;
        if (row0 + r < n) {
            float4 v = X4[idx];
            float* p = &Xs[r * 65 + c4 * 4];
            p[0] = v.x; p[1] = v.y; p[2] = v.z; p[3] = v.w;
        }
    }
    __syncthreads();

    int r = tid >> 2;
    int cs = (tid & 3) * 16;
    int row = row0 + r;
    if (row >= n) return;

    float acc[16];
    #pragma unroll
    for (int c = 0; c < 16; c++) acc[c] = 0.f;
    #pragma unroll
    for (int k = 0; k < 64; k++) {
        float xv = Xs[r * 65 + k];
        const float4* wr = (const float4*)&Ws[k * 64 + cs];
        #pragma unroll
        for (int c4 = 0; c4 < 4; c4++) {
            float4 wv = wr[c4];
            acc[c4 * 4 + 0] += xv * wv.x;
            acc[c4 * 4 + 1] += xv * wv.y;
            acc[c4 * 4 + 2] += xv * wv.z;
            acc[c4 * 4 + 3] += xv * wv.w;
        }
    }

    __half2 hh[8];
    #pragma unroll
    for (int i = 0; i < 8; i++) hh[i] = __floats2half2_rn(acc[2 * i], acc[2 * i + 1]);
    uint4* dstp = (uint4*)(g_xwA + (size_t)row * 64 + cs);
    dstp[0] = ((uint4*)hh)[0];
    dstp[1] = ((uint4*)hh)[1];
}

// ---- gather core: 4 threads/node, each accumulates 16 features in fp32 ----
#define ACC8(v, nv, base) { const __half2* _h = (const __half2*)&(v); \
    float2 _t0 = __half22float2(_h[0]), _t1 = __half22float2(_h[1]); \
    float2 _t2 = __half22float2(_h[2]), _t3 = __half22float2(_h[3]); \
    a[(base)+0] += _t0.x * (nv); a[(base)+1] += _t0.y * (nv); \
    a[(base)+2] += _t1.x * (nv); a[(base)+3] += _t1.y * (nv); \
    a[(base)+4] += _t2.x * (nv); a[(base)+5] += _t2.y * (nv); \
    a[(base)+6] += _t3.x * (nv); a[(base)+7] += _t3.y * (nv); }

__device__ __forceinline__ void gather_core16(const __half* __restrict__ xwh,
                                              int node, int j,
                                              const float* __restrict__ bias,
                                              float* a /*[16]*/)
{
    int start = __ldg(g_row + node);
    int end   = __ldg(g_row + node + 1);
    float dv = __ldg(g_deg + node);
    float inv = dv * dv;

    const uint4* xw = (const uint4*)xwh;   // 8 slots of 8 halfs per row

    // bias + self-loop
    {
        uint4 v0 = __ldg(&xw[(size_t)node * 8 + j * 2]);
        uint4 v1 = __ldg(&xw[(size_t)node * 8 + j * 2 + 1]);
        const float4* b4 = (const float4*)(bias + j * 16);
        float4 b0 = __ldg(b4), b1 = __ldg(b4 + 1), b2 = __ldg(b4 + 2), b3 = __ldg(b4 + 3);
        #pragma unroll
        for (int q = 0; q < 16; q++) a[q] = 0.f;
        ACC8(v0, inv, 0); ACC8(v1, inv, 8);
        a[0] += b0.x; a[1] += b0.y; a[2] += b0.z; a[3] += b0.w;
        a[4] += b1.x; a[5] += b1.y; a[6] += b1.z; a[7] += b1.w;
        a[8] += b2.x; a[9] += b2.y; a[10] += b2.z; a[11] += b2.w;
        a[12] += b3.x; a[13] += b3.y; a[14] += b3.z; a[15] += b3.w;
    }

    int e = start;
    for (; e + 1 < end; e += 2) {
        int2 p0 = __ldg(g_edge + e);
        int2 p1 = __ldg(g_edge + e + 1);
        uint4 u0 = __ldg(&xw[(size_t)p0.x * 8 + j * 2]);
        uint4 u1 = __ldg(&xw[(size_t)p0.x * 8 + j * 2 + 1]);
        uint4 u2 = __ldg(&xw[(size_t)p1.x * 8 + j * 2]);
        uint4 u3 = __ldg(&xw[(size_t)p1.x * 8 + j * 2 + 1]);
        float n0 = __int_as_float(p0.y);
        float n1 = __int_as_float(p1.y);
        ACC8(u0, n0, 0); ACC8(u1, n0, 8);
        ACC8(u2, n1, 0); ACC8(u3, n1, 8);
    }
    if (e < end) {
        int2 p0 = __ldg(g_edge + e);
        uint4 u0 = __ldg(&xw[(size_t)p0.x * 8 + j * 2]);
        uint4 u1 = __ldg(&xw[(size_t)p0.x * 8 + j * 2 + 1]);
        float n0 = __int_as_float(p0.y);
        ACC8(u0, n0, 0); ACC8(u1, n0, 8);
    }
}

// -------------------- fused: gather(prev) + bias -> relu -> @Wnext -> xw(next) --------------------
// 256 threads = 64 nodes x 4 threads
__global__ __launch_bounds__(256) void k_fused(
    const float* __restrict__ bias, const float* __restrict__ W,
    int in_is_A, int n)
{
    __shared__ float Ws[64 * 64];
    __shared__ float Xs[64 * 65];

    const __half* xin = in_is_A ? g_xwA : g_xwB;
    __half* xout      = in_is_A ? g_xwB : g_xwA;

    int tid = threadIdx.x;
    int row0 = blockIdx.x * 64;

    const float4* W4 = (const float4*)W;
    float4* Ws4 = (float4*)Ws;
    #pragma unroll
    for (int i = 0; i < 4; i++) Ws4[tid + 256 * i] = W4[tid + 256 * i];

    int node_l = tid >> 2;
    int j = tid & 3;
    int node = row0 + node_l;

    if (node < n) {
        float a[16];
        gather_core16(xin, node, j, bias, a);
        float* p = &Xs[node_l * 65 + j * 16];
        #pragma unroll
        for (int q = 0; q < 16; q++) p[q] = fmaxf(a[q], 0.f);   // relu for next layer input
    }
    __syncthreads();

    int r = tid >> 2;
    int cs = (tid & 3) * 16;
    int row = row0 + r;
    if (row >= n) return;

    float acc[16];
    #pragma unroll
    for (int c = 0; c < 16; c++) acc[c] = 0.f;
    #pragma unroll
    for (int k = 0; k < 64; k++) {
        float xv = Xs[r * 65 + k];
        const float4* wr = (const float4*)&Ws[k * 64 + cs];
        #pragma unroll
        for (int c4 = 0; c4 < 4; c4++) {
            float4 wv = wr[c4];
            acc[c4 * 4 + 0] += xv * wv.x;
            acc[c4 * 4 + 1] += xv * wv.y;
            acc[c4 * 4 + 2] += xv * wv.z;
            acc[c4 * 4 + 3] += xv * wv.w;
        }
    }

    __half2 hh[8];
    #pragma unroll
    for (int i = 0; i < 8; i++) hh[i] = __floats2half2_rn(acc[2 * i], acc[2 * i + 1]);
    uint4* dstp = (uint4*)(xout + (size_t)row * 64 + cs);
    dstp[0] = ((uint4*)hh)[0];
    dstp[1] = ((uint4*)hh)[1];
}

// -------------------- fused final gather + MLP readout + pooling --------------------
// 256 threads = 64 nodes x 4 threads; reads g_xwA (layer-2 xw)
__global__ __launch_bounds__(256) void k_gather_readout(
    const float* __restrict__ bias,
    const float* __restrict__ Wr0, const float* __restrict__ br0,
    const float* __restrict__ Wr1, const float* __restrict__ br1,
    const int* __restrict__ batch, int n)
{
    __shared__ float aggS[64 * 65];
    __shared__ float W0s[64 * 32];
    __shared__ float W1s[32];
    __shared__ float b0s[32];

    int tid = threadIdx.x;
    for (int i = tid; i < 2048; i += 256) W0s[i] = Wr0[i];
    if (tid < 32) { W1s[tid] = Wr1[tid]; b0s[tid] = br0[tid]; }

    int node_l = tid >> 2;
    int j = tid & 3;
    int node = blockIdx.x * 64 + node_l;
    bool valid = (node < n);

    if (valid) {
        float a[16];
        gather_core16(g_xwA, node, j, bias, a);   // no relu on last GNN layer
        float* p = &aggS[node_l * 65 + j * 16];
        #pragma unroll
        for (int q = 0; q < 16; q++) p[q] = a[q];
    }
    __syncthreads();

    float s = 0.f, cv = 0.f;
    int g = -1;
    if (valid) {
        int c0 = j * 8;
        float acc[8];
        #pragma unroll
        for (int q = 0; q < 8; q++) acc[q] = b0s[c0 + q];
        const float* row = &aggS[node_l * 65];
        #pragma unroll
        for (int k = 0; k < 64; k++) {
            float v = row[k];
            const float4 w0 = *(const float4*)&W0s[k * 32 + c0];
            const float4 w1 = *(const float4*)&W0s[k * 32 + c0 + 4];
            acc[0] += v * w0.x; acc[1] += v * w0.y; acc[2] += v * w0.z; acc[3] += v * w0.w;
            acc[4] += v * w1.x; acc[5] += v * w1.y; acc[6] += v * w1.z; acc[7] += v * w1.w;
        }
        #pragma unroll
        for (int q = 0; q < 8; q++) s += fmaxf(acc[q], 0.f) * W1s[c0 + q];
        g = __ldg(batch + node);
    }

    // sum the 4 partials of each node (aligned 4-lane groups)
    const unsigned full = 0xffffffffu;
    s += __shfl_xor_sync(full, s, 2);
    s += __shfl_xor_sync(full, s, 1);

    if (valid && j == 0) { s += __ldg(br1); cv = 1.f; }
    else { s = 0.f; }

    // warp segmented scan over sorted graph ids (8 nodes per warp)
    int lane = tid & 31;
    #pragma unroll
    for (int off = 1; off < 32; off <<= 1) {
        float so = __shfl_up_sync(full, s, off);
        float co = __shfl_up_sync(full, cv, off);
        int go = __shfl_up_sync(full, g, off);
        if (lane >= off && go == g) { s += so; cv += co; }
    }
    int gn = __shfl_down_sync(full, g, 1);
    if ((lane == 31 || gn != g) && g >= 0) {
        atomicAdd(&g_sums[g], s);
        atomicAdd(&g_cnt[g], cv);
    }
}

__global__ void k_finalize(float* __restrict__ out) {
    int g = threadIdx.x;
    out[g] = g_sums[g] / fmaxf(g_cnt[g], 1.0f);
}

// -------------------- launch --------------------
extern "C" void kernel_launch(void* const* d_in, const int* in_sizes, int n_in,
                              void* d_out, int out_size)
{
    const float* x   = (const float*)d_in[0];
    const int*   ei  = (const int*)d_in[1];
    const float* ew  = (const float*)d_in[2];
    const int* batch = (const int*)d_in[3];
    const float* W0  = (const float*)d_in[4];
    const float* b0  = (const float*)d_in[5];
    const float* W1  = (const float*)d_in[6];
    const float* b1  = (const float*)d_in[7];
    const float* W2  = (const float*)d_in[8];
    const float* b2  = (const float*)d_in[9];
    const float* Wr0 = (const float*)d_in[10];
    const float* br0 = (const float*)d_in[11];
    const float* Wr1 = (const float*)d_in[12];
    const float* br1 = (const float*)d_in[13];
    float* out = (float*)d_out;

    int n = in_sizes[0] / HID;       // 100000
    int E = in_sizes[2];             // 1600000
    const int* src = ei;
    const int* dst = ei + E;

    int nb = (n + 1023) / 1024;

    // ---- CSR build ----
    k_init<<<(n + 255) / 256, 256>>>(n);
    k_deg_hist<<<(E + 255) / 256, 256>>>(dst, ew, E);
    k_scanA<<<nb, 1024>>>(n);
    k_scanB<<<1, 128>>>(nb);
    k_scanC<<<nb, 1024>>>(n, E);
    k_fill<<<(E + 255) / 256, 256>>>(src, dst, ew, E);

    int gb = (n + 63) / 64;

    // layer 0 GEMM: x -> xwA
    k_gemm0<<<gb, 256>>>(x, W0, n);
    // boundary 0->1: gather(xwA)+b0, relu, @W1 -> xwB
    k_fused<<<gb, 256>>>(b0, W1, 1, n);
    // boundary 1->2: gather(xwB)+b1, relu, @W2 -> xwA
    k_fused<<<gb, 256>>>(b1, W2, 0, n);
    // final: gather(xwA)+b2 -> MLP readout -> pooled mean
    k_gather_readout<<<gb, 256>>>(b2, Wr0, br0, Wr1, br1, batch, n);

    k_finalize<<<1, 256>>>(out);
}